// round 1
// baseline (speedup 1.0000x reference)
#include <cuda_runtime.h>
#include <math.h>

// Problem constants
#define BB 2
#define SS 2048
#define DD 1024
#define HH 16
#define HD 64
#define MROWS (BB*SS)          // 4096

// ---------------- scratch (device globals; no allocation) ----------------
__device__ float g_xn  [MROWS*DD];          // 16 MB
__device__ float g_q   [BB*HH*SS*HD];       // 16 MB  [B,H,S,HD]
__device__ float g_k   [BB*HH*SS*HD];
__device__ float g_v   [BB*HH*SS*HD];
__device__ float g_ctx [MROWS*DD];          // 16 MB  [B,S,D] head-interleaved
__device__ float g_outb[MROWS*DD];
__device__ float g_gate[MROWS*DD];

// ---------------- helpers ----------------
__device__ __forceinline__ float tfr(float x) {
    unsigned u;
    asm("cvt.rna.tf32.f32 %0, %1;" : "=r"(u) : "f"(x));
    return __uint_as_float(u);
}

__device__ __forceinline__ void mma8(float* d, const unsigned* a, const unsigned* b) {
    asm volatile(
        "mma.sync.aligned.m16n8k8.row.col.f32.tf32.tf32.f32 "
        "{%0,%1,%2,%3}, {%4,%5,%6,%7}, {%8,%9}, {%0,%1,%2,%3};"
        : "+f"(d[0]), "+f"(d[1]), "+f"(d[2]), "+f"(d[3])
        : "r"(a[0]), "r"(a[1]), "r"(a[2]), "r"(a[3]),
          "r"(b[0]), "r"(b[1]));
}

// ---------------- LayerNorm ----------------
__global__ __launch_bounds__(256) void ln_kernel(
    const float* __restrict__ x, const float* __restrict__ gamma,
    const float* __restrict__ beta)
{
    const int row = blockIdx.x;
    const int t = threadIdx.x;
    const float4 v = reinterpret_cast<const float4*>(x + (size_t)row * DD)[t];
    float s  = v.x + v.y + v.z + v.w;
    float s2 = v.x*v.x + v.y*v.y + v.z*v.z + v.w*v.w;
    #pragma unroll
    for (int o = 16; o > 0; o >>= 1) {
        s  += __shfl_xor_sync(0xFFFFFFFFu, s,  o);
        s2 += __shfl_xor_sync(0xFFFFFFFFu, s2, o);
    }
    __shared__ float ws[8], ws2[8];
    if ((t & 31) == 0) { ws[t >> 5] = s; ws2[t >> 5] = s2; }
    __syncthreads();
    float st = 0.f, st2 = 0.f;
    #pragma unroll
    for (int i = 0; i < 8; i++) { st += ws[i]; st2 += ws2[i]; }
    const float mu  = st * (1.f / DD);
    const float var = st2 * (1.f / DD) - mu * mu;
    const float inv = rsqrtf(var + 1e-5f);
    const float4 gm = reinterpret_cast<const float4*>(gamma)[t];
    const float4 bt = reinterpret_cast<const float4*>(beta)[t];
    float4 o;
    o.x = (v.x - mu) * inv * gm.x + bt.x;
    o.y = (v.y - mu) * inv * gm.y + bt.y;
    o.z = (v.z - mu) * inv * gm.z + bt.z;
    o.w = (v.w - mu) * inv * gm.w + bt.w;
    reinterpret_cast<float4*>(g_xn + (size_t)row * DD)[t] = o;
}

// ---------------- tf32 tensor-core GEMM: C = A[MxK] * B[KxN] + bias ----------------
// mode 0: plain row-major store to C.  mode 1: scatter into g_q/g_k/g_v ([B,H,S,HD]).
__global__ __launch_bounds__(256) void gemm_tf32(
    const float* __restrict__ A, const float* __restrict__ Bw,
    const float* __restrict__ bias, float* __restrict__ C,
    int M, int N, int K, int mode)
{
    __shared__ float As[2][16][128 + 4];   // [k][m]
    __shared__ float Bs[2][16][128 + 4];   // [k][n]

    const int tid  = threadIdx.x;
    const int warp = tid >> 5, lane = tid & 31;
    const int wm = warp >> 1, wn = warp & 1;
    const int g  = lane >> 2, tg = lane & 3;
    const int brow = blockIdx.y << 7, bcol = blockIdx.x << 7;

    float acc[2][8][4];
    #pragma unroll
    for (int i = 0; i < 2; i++)
        #pragma unroll
        for (int j = 0; j < 8; j++)
            #pragma unroll
            for (int k = 0; k < 4; k++) acc[i][j][k] = 0.f;

    const int a_row0 = tid >> 2;            // + 64*i
    const int a_q    = (tid & 3) << 2;
    const int b_k0   = tid >> 5;            // + 8*i
    const int b_q    = (tid & 31) << 2;

    float4 ra[2], rb[2];

    auto gload = [&](int kt) {
        #pragma unroll
        for (int i = 0; i < 2; i++) {
            ra[i] = *reinterpret_cast<const float4*>(
                &A[(size_t)(brow + a_row0 + 64 * i) * K + kt * 16 + a_q]);
            rb[i] = *reinterpret_cast<const float4*>(
                &Bw[(size_t)(kt * 16 + b_k0 + 8 * i) * N + bcol + b_q]);
        }
    };
    auto sstore = [&](int buf) {
        #pragma unroll
        for (int i = 0; i < 2; i++) {
            const int r = a_row0 + 64 * i;
            As[buf][a_q + 0][r] = tfr(ra[i].x);
            As[buf][a_q + 1][r] = tfr(ra[i].y);
            As[buf][a_q + 2][r] = tfr(ra[i].z);
            As[buf][a_q + 3][r] = tfr(ra[i].w);
            float4 t;
            t.x = tfr(rb[i].x); t.y = tfr(rb[i].y);
            t.z = tfr(rb[i].z); t.w = tfr(rb[i].w);
            *reinterpret_cast<float4*>(&Bs[buf][b_k0 + 8 * i][b_q]) = t;
        }
    };
    auto compute = [&](int buf) {
        #pragma unroll
        for (int ks = 0; ks < 16; ks += 8) {
            unsigned af[2][4];
            #pragma unroll
            for (int mt = 0; mt < 2; mt++) {
                const int mr = (wm << 5) + (mt << 4) + g;
                af[mt][0] = __float_as_uint(As[buf][ks + tg][mr]);
                af[mt][1] = __float_as_uint(As[buf][ks + tg][mr + 8]);
                af[mt][2] = __float_as_uint(As[buf][ks + tg + 4][mr]);
                af[mt][3] = __float_as_uint(As[buf][ks + tg + 4][mr + 8]);
            }
            unsigned bf[8][2];
            #pragma unroll
            for (int nt = 0; nt < 8; nt++) {
                const int nc = (wn << 6) + (nt << 3) + g;
                bf[nt][0] = __float_as_uint(Bs[buf][ks + tg][nc]);
                bf[nt][1] = __float_as_uint(Bs[buf][ks + tg + 4][nc]);
            }
            #pragma unroll
            for (int mt = 0; mt < 2; mt++)
                #pragma unroll
                for (int nt = 0; nt < 8; nt++)
                    mma8(acc[mt][nt], af[mt], bf[nt]);
        }
    };

    gload(0); sstore(0); __syncthreads();
    const int nk = K >> 4;
    for (int kt = 0; kt < nk; kt++) {
        const int cur = kt & 1;
        if (kt + 1 < nk) gload(kt + 1);
        compute(cur);
        if (kt + 1 < nk) sstore(cur ^ 1);
        __syncthreads();
    }

    // epilogue
    #pragma unroll
    for (int mt = 0; mt < 2; mt++) {
        #pragma unroll
        for (int nt = 0; nt < 8; nt++) {
            const int r0 = brow + (wm << 5) + (mt << 4) + g;
            const int c0 = bcol + (wn << 6) + (nt << 3) + (tg << 1);
            #pragma unroll
            for (int ii = 0; ii < 4; ii++) {
                const int r = r0 + ((ii >> 1) << 3);
                const int c = c0 + (ii & 1);
                const float v = acc[mt][nt][ii] + bias[c];
                if (mode == 0) {
                    C[(size_t)r * N + c] = v;
                } else {
                    const int which = c >> 10;
                    const int h = (c >> 6) & 15;
                    const int d = c & 63;
                    const int b = r >> 11;
                    const int s = r & 2047;
                    const size_t idx = ((size_t)((b * HH + h) * SS + s)) * HD + d;
                    if (which == 0)      g_q[idx] = v;
                    else if (which == 1) g_k[idx] = v;
                    else                 g_v[idx] = v;
                }
            }
        }
    }
}

// ---------------- flash attention (tf32 MMA, online softmax) ----------------
#define APAD 68
#define ATT_SMEM_BYTES ((128*APAD + 64*APAD + 64*APAD + 128*APAD + 3*128) * 4)

__global__ __launch_bounds__(256) void attn_kernel()
{
    extern __shared__ float sm[];
    float* Qs  = sm;                       // [128][APAD]
    float* Ks  = Qs + 128 * APAD;          // [64][APAD]
    float* Vs  = Ks + 64 * APAD;           // [64][APAD]
    float* Ps  = Vs + 64 * APAD;           // [128][APAD]
    float* m_s = Ps + 128 * APAD;          // [128]
    float* l_s = m_s + 128;                // [128]
    float* rs  = l_s + 128;                // [128]

    const int tid  = threadIdx.x;
    const int warp = tid >> 5, lane = tid & 31;
    const int wm = warp >> 1, wn = warp & 1;
    const int g  = lane >> 2, tg = lane & 3;
    const int bh = blockIdx.y;
    const int q0 = blockIdx.x << 7;

    const float* Qg = g_q + (size_t)bh * SS * HD;
    const float* Kg = g_k + (size_t)bh * SS * HD;
    const float* Vg = g_v + (size_t)bh * SS * HD;

    // load Q tile (128 x 64), tf32-rounded
    #pragma unroll
    for (int i = 0; i < 8; i++) {
        const int id = tid + (i << 8);
        const int r = id >> 4, cq = (id & 15) << 2;
        const float4 v = *reinterpret_cast<const float4*>(&Qg[(size_t)(q0 + r) * HD + cq]);
        Qs[r * APAD + cq + 0] = tfr(v.x);
        Qs[r * APAD + cq + 1] = tfr(v.y);
        Qs[r * APAD + cq + 2] = tfr(v.z);
        Qs[r * APAD + cq + 3] = tfr(v.w);
    }
    if (tid < 128) { m_s[tid] = -1e30f; l_s[tid] = 0.f; }

    float oacc[2][4][4];
    #pragma unroll
    for (int i = 0; i < 2; i++)
        #pragma unroll
        for (int j = 0; j < 4; j++)
            #pragma unroll
            for (int k = 0; k < 4; k++) oacc[i][j][k] = 0.f;

    for (int kt = 0; kt < SS / 64; kt++) {
        __syncthreads();   // previous iter's reads of Ks/Vs/Ps done
        #pragma unroll
        for (int i = 0; i < 4; i++) {
            const int id = tid + (i << 8);
            const int r = id >> 4, cq = (id & 15) << 2;
            const size_t off = (size_t)(kt * 64 + r) * HD + cq;
            const float4 kv = *reinterpret_cast<const float4*>(&Kg[off]);
            const float4 vv = *reinterpret_cast<const float4*>(&Vg[off]);
            Ks[r * APAD + cq + 0] = tfr(kv.x);
            Ks[r * APAD + cq + 1] = tfr(kv.y);
            Ks[r * APAD + cq + 2] = tfr(kv.z);
            Ks[r * APAD + cq + 3] = tfr(kv.w);
            Vs[r * APAD + cq + 0] = tfr(vv.x);
            Vs[r * APAD + cq + 1] = tfr(vv.y);
            Vs[r * APAD + cq + 2] = tfr(vv.z);
            Vs[r * APAD + cq + 3] = tfr(vv.w);
        }
        __syncthreads();

        // S = Q * K^T  (M=128 q, N=64 keys, K=64 hd)
        float sacc[2][4][4];
        #pragma unroll
        for (int i = 0; i < 2; i++)
            #pragma unroll
            for (int j = 0; j < 4; j++)
                #pragma unroll
                for (int k = 0; k < 4; k++) sacc[i][j][k] = 0.f;

        #pragma unroll
        for (int ks = 0; ks < 64; ks += 8) {
            unsigned af[2][4];
            #pragma unroll
            for (int mt = 0; mt < 2; mt++) {
                const int mr = (wm << 5) + (mt << 4) + g;
                af[mt][0] = __float_as_uint(Qs[mr * APAD + ks + tg]);
                af[mt][1] = __float_as_uint(Qs[(mr + 8) * APAD + ks + tg]);
                af[mt][2] = __float_as_uint(Qs[mr * APAD + ks + tg + 4]);
                af[mt][3] = __float_as_uint(Qs[(mr + 8) * APAD + ks + tg + 4]);
            }
            unsigned bf[4][2];
            #pragma unroll
            for (int nt = 0; nt < 4; nt++) {
                const int nc = (wn << 5) + (nt << 3) + g;
                bf[nt][0] = __float_as_uint(Ks[nc * APAD + ks + tg]);
                bf[nt][1] = __float_as_uint(Ks[nc * APAD + ks + tg + 4]);
            }
            #pragma unroll
            for (int mt = 0; mt < 2; mt++)
                #pragma unroll
                for (int nt = 0; nt < 4; nt++)
                    mma8(sacc[mt][nt], af[mt], bf[nt]);
        }

        // write scaled scores to Ps
        #pragma unroll
        for (int mt = 0; mt < 2; mt++)
            #pragma unroll
            for (int nt = 0; nt < 4; nt++) {
                const int r = (wm << 5) + (mt << 4) + g;
                const int c = (wn << 5) + (nt << 3) + (tg << 1);
                Ps[r * APAD + c]           = sacc[mt][nt][0] * 0.125f;
                Ps[r * APAD + c + 1]       = sacc[mt][nt][1] * 0.125f;
                Ps[(r + 8) * APAD + c]     = sacc[mt][nt][2] * 0.125f;
                Ps[(r + 8) * APAD + c + 1] = sacc[mt][nt][3] * 0.125f;
            }
        __syncthreads();

        // online softmax: one thread per q-row
        if (tid < 128) {
            const float mo = m_s[tid];
            float mx = mo;
            float* pr = Ps + tid * APAD;
            #pragma unroll 8
            for (int j = 0; j < 64; j++) mx = fmaxf(mx, pr[j]);
            float sum = 0.f;
            #pragma unroll 8
            for (int j = 0; j < 64; j++) {
                const float p = tfr(__expf(pr[j] - mx));
                pr[j] = p;
                sum += p;
            }
            const float f = __expf(mo - mx);
            l_s[tid] = l_s[tid] * f + sum;
            m_s[tid] = mx;
            rs[tid]  = f;
        }
        __syncthreads();

        // rescale running output accumulators
        #pragma unroll
        for (int mt = 0; mt < 2; mt++) {
            const int r = (wm << 5) + (mt << 4) + g;
            const float f0 = rs[r], f1 = rs[r + 8];
            #pragma unroll
            for (int nt = 0; nt < 4; nt++) {
                oacc[mt][nt][0] *= f0; oacc[mt][nt][1] *= f0;
                oacc[mt][nt][2] *= f1; oacc[mt][nt][3] *= f1;
            }
        }

        // O += P * V  (M=128 q, N=64 hd, K=64 keys)
        #pragma unroll
        for (int ks = 0; ks < 64; ks += 8) {
            unsigned af[2][4];
            #pragma unroll
            for (int mt = 0; mt < 2; mt++) {
                const int mr = (wm << 5) + (mt << 4) + g;
                af[mt][0] = __float_as_uint(Ps[mr * APAD + ks + tg]);
                af[mt][1] = __float_as_uint(Ps[(mr + 8) * APAD + ks + tg]);
                af[mt][2] = __float_as_uint(Ps[mr * APAD + ks + tg + 4]);
                af[mt][3] = __float_as_uint(Ps[(mr + 8) * APAD + ks + tg + 4]);
            }
            unsigned bf[4][2];
            #pragma unroll
            for (int nt = 0; nt < 4; nt++) {
                const int nc = (wn << 5) + (nt << 3) + g;
                bf[nt][0] = __float_as_uint(Vs[(ks + tg) * APAD + nc]);
                bf[nt][1] = __float_as_uint(Vs[(ks + tg + 4) * APAD + nc]);
            }
            #pragma unroll
            for (int mt = 0; mt < 2; mt++)
                #pragma unroll
                for (int nt = 0; nt < 4; nt++)
                    mma8(oacc[mt][nt], af[mt], bf[nt]);
        }
    }

    // final normalize + write ctx in [B,S,H*HD] layout
    const int b = bh >> 4, h = bh & 15;
    #pragma unroll
    for (int mt = 0; mt < 2; mt++) {
        const int r = (wm << 5) + (mt << 4) + g;
        const float inv0 = 1.f / l_s[r];
        const float inv1 = 1.f / l_s[r + 8];
        #pragma unroll
        for (int nt = 0; nt < 4; nt++) {
            const int c = (wn << 5) + (nt << 3) + (tg << 1);
            const size_t base0 = ((size_t)(b * SS + q0 + r)) * DD + h * HD + c;
            const size_t base1 = ((size_t)(b * SS + q0 + r + 8)) * DD + h * HD + c;
            g_ctx[base0]     = oacc[mt][nt][0] * inv0;
            g_ctx[base0 + 1] = oacc[mt][nt][1] * inv0;
            g_ctx[base1]     = oacc[mt][nt][2] * inv1;
            g_ctx[base1 + 1] = oacc[mt][nt][3] * inv1;
        }
    }
}

// ---------------- final: out * sigmoid(gate) + residual ----------------
__global__ __launch_bounds__(256) void final_kernel(
    const float* __restrict__ x, float* __restrict__ out)
{
    const int i = blockIdx.x * 256 + threadIdx.x;
    const float4 o  = reinterpret_cast<const float4*>(g_outb)[i];
    const float4 gt = reinterpret_cast<const float4*>(g_gate)[i];
    const float4 xv = reinterpret_cast<const float4*>(x)[i];
    float4 r;
    r.x = o.x / (1.f + __expf(-gt.x)) + xv.x;
    r.y = o.y / (1.f + __expf(-gt.y)) + xv.y;
    r.z = o.z / (1.f + __expf(-gt.z)) + xv.z;
    r.w = o.w / (1.f + __expf(-gt.w)) + xv.w;
    reinterpret_cast<float4*>(out)[i] = r;
}

// ---------------- launch ----------------
extern "C" void kernel_launch(void* const* d_in, const int* in_sizes, int n_in,
                              void* d_out, int out_size)
{
    const float* x      = (const float*)d_in[0];
    const float* gamma  = (const float*)d_in[1];
    const float* beta   = (const float*)d_in[2];
    const float* w_qkv  = (const float*)d_in[3];
    const float* b_qkv  = (const float*)d_in[4];
    const float* w_out  = (const float*)d_in[5];
    const float* b_out  = (const float*)d_in[6];
    const float* w_gate = (const float*)d_in[7];
    const float* b_gate = (const float*)d_in[8];
    float* out = (float*)d_out;

    float *p_xn, *p_ctx, *p_out, *p_gate;
    cudaGetSymbolAddress((void**)&p_xn,   g_xn);
    cudaGetSymbolAddress((void**)&p_ctx,  g_ctx);
    cudaGetSymbolAddress((void**)&p_out,  g_outb);
    cudaGetSymbolAddress((void**)&p_gate, g_gate);

    cudaFuncSetAttribute(attn_kernel,
                         cudaFuncAttributeMaxDynamicSharedMemorySize,
                         ATT_SMEM_BYTES);

    ln_kernel<<<MROWS, 256>>>(x, gamma, beta);

    // QKV: [4096,1024] @ [1024,3072] -> scatter to q/k/v
    gemm_tf32<<<dim3(3 * DD / 128, MROWS / 128), 256>>>(
        p_xn, w_qkv, b_qkv, nullptr, MROWS, 3 * DD, DD, 1);

    attn_kernel<<<dim3(SS / 128, BB * HH), 256, ATT_SMEM_BYTES>>>();

    // out proj and gate proj
    gemm_tf32<<<dim3(DD / 128, MROWS / 128), 256>>>(
        p_ctx, w_out, b_out, p_out, MROWS, DD, DD, 0);
    gemm_tf32<<<dim3(DD / 128, MROWS / 128), 256>>>(
        p_xn, w_gate, b_gate, p_gate, MROWS, DD, DD, 0);

    final_kernel<<<MROWS * DD / 1024, 256>>>(x, out);
}

// round 2
// speedup vs baseline: 1.4272x; 1.4272x over previous
#include <cuda_runtime.h>
#include <cuda_bf16.h>
#include <math.h>

#define BB 2
#define SS 2048
#define DD 1024
#define HH 16
#define HD 64
#define MROWS (BB*SS)          // 4096

// ---------------- scratch (device globals; no allocation) ----------------
__device__ __align__(16) unsigned g_xn  [MROWS*DD/2];       // bf16 [M][D]
__device__ __align__(16) unsigned g_q   [BB*HH*SS*HD/2];    // bf16 [B,H,S,HD]
__device__ __align__(16) unsigned g_k   [BB*HH*SS*HD/2];
__device__ __align__(16) unsigned g_v   [BB*HH*SS*HD/2];
__device__ __align__(16) unsigned g_ctx [MROWS*DD/2];       // bf16 [B,S,D]
__device__ __align__(16) float    g_outb[MROWS*DD];         // f32
__device__ __align__(16) unsigned g_wqT [3*DD*DD/2];        // bf16 [3D][D] (W^T)
__device__ __align__(16) unsigned g_woT [DD*DD/2];          // bf16 [D][D]
__device__ __align__(16) unsigned g_wgT [DD*DD/2];

// ---------------- helpers ----------------
__device__ __forceinline__ float ex2(float x) {
    float y; asm("ex2.approx.ftz.f32 %0, %1;" : "=f"(y) : "f"(x)); return y;
}
// pack (lo, hi) -> bf16x2 ; PTX cvt packs first source into the HIGH half
__device__ __forceinline__ unsigned pk(float lo, float hi) {
    unsigned r; asm("cvt.rn.bf16x2.f32 %0, %1, %2;" : "=r"(r) : "f"(hi), "f"(lo));
    return r;
}
__device__ __forceinline__ void mma16(float* d, const unsigned* a, const unsigned* b) {
    asm volatile(
        "mma.sync.aligned.m16n8k16.row.col.f32.bf16.bf16.f32 "
        "{%0,%1,%2,%3}, {%4,%5,%6,%7}, {%8,%9}, {%0,%1,%2,%3};"
        : "+f"(d[0]), "+f"(d[1]), "+f"(d[2]), "+f"(d[3])
        : "r"(a[0]), "r"(a[1]), "r"(a[2]), "r"(a[3]),
          "r"(b[0]), "r"(b[1]));
}

// ---------------- LayerNorm -> bf16 ----------------
__global__ __launch_bounds__(256) void ln_kernel(
    const float* __restrict__ x, const float* __restrict__ gamma,
    const float* __restrict__ beta)
{
    const int row = blockIdx.x;
    const int t = threadIdx.x;
    const float4 v = reinterpret_cast<const float4*>(x + (size_t)row * DD)[t];
    float s  = v.x + v.y + v.z + v.w;
    float s2 = v.x*v.x + v.y*v.y + v.z*v.z + v.w*v.w;
    #pragma unroll
    for (int o = 16; o > 0; o >>= 1) {
        s  += __shfl_xor_sync(0xFFFFFFFFu, s,  o);
        s2 += __shfl_xor_sync(0xFFFFFFFFu, s2, o);
    }
    __shared__ float ws[8], ws2[8];
    if ((t & 31) == 0) { ws[t >> 5] = s; ws2[t >> 5] = s2; }
    __syncthreads();
    float st = 0.f, st2 = 0.f;
    #pragma unroll
    for (int i = 0; i < 8; i++) { st += ws[i]; st2 += ws2[i]; }
    const float mu  = st * (1.f / DD);
    const float var = st2 * (1.f / DD) - mu * mu;
    const float inv = rsqrtf(var + 1e-5f);
    const float4 gm = reinterpret_cast<const float4*>(gamma)[t];
    const float4 bt = reinterpret_cast<const float4*>(beta)[t];
    uint2 o;
    o.x = pk((v.x - mu) * inv * gm.x + bt.x, (v.y - mu) * inv * gm.y + bt.y);
    o.y = pk((v.z - mu) * inv * gm.z + bt.z, (v.w - mu) * inv * gm.w + bt.w);
    reinterpret_cast<uint2*>(g_xn)[row * 256 + t] = o;
}

// ---------------- weight transpose + fp32->bf16 ----------------
__global__ __launch_bounds__(256) void wconv(
    const float* __restrict__ src, __nv_bfloat16* __restrict__ dst, int K, int N)
{
    __shared__ float s[32][33];
    const int tx = threadIdx.x, ty = threadIdx.y;
    const int n0 = blockIdx.x << 5, k0 = blockIdx.y << 5;
    #pragma unroll
    for (int i = 0; i < 4; i++)
        s[ty + 8*i][tx] = src[(size_t)(k0 + ty + 8*i) * N + n0 + tx];
    __syncthreads();
    #pragma unroll
    for (int i = 0; i < 4; i++)
        dst[(size_t)(n0 + ty + 8*i) * K + k0 + tx] = __float2bfloat16(s[tx][ty + 8*i]);
}

// ---------------- bf16 tensor GEMM: C = A[MxK] * BT[NxK]^T + bias ----------------
// mode 0: f32 store to C. mode 1: scatter bf16 into g_q/g_k/g_v.
// mode 2: fused gate: C[r,c] = fuse_o[r,c]*sigmoid(acc+bias) + fuse_x[r,c]
__global__ __launch_bounds__(256) void gemm_bf16(
    const __nv_bfloat16* __restrict__ A, const __nv_bfloat16* __restrict__ BT,
    const float* __restrict__ bias, float* __restrict__ C,
    const float* __restrict__ fuse_o, const float* __restrict__ fuse_x,
    int M, int N, int K, int mode)
{
    __shared__ unsigned As[2][128][20];   // [m][kp]  kp = k/2
    __shared__ unsigned Bs[2][128][20];   // [n][kp]

    const int tid  = threadIdx.x;
    const int warp = tid >> 5, lane = tid & 31;
    const int wm = warp >> 1, wn = warp & 1;
    const int g  = lane >> 2, tg = lane & 3;
    const int brow = blockIdx.y << 7, bcol = blockIdx.x << 7;

    float acc[2][8][4];
    #pragma unroll
    for (int i = 0; i < 2; i++)
        #pragma unroll
        for (int j = 0; j < 8; j++)
            #pragma unroll
            for (int k = 0; k < 4; k++) acc[i][j][k] = 0.f;

    const int arow = tid >> 1;            // tile row (both A and BT)
    const int akp  = (tid & 1) << 3;      // kp offset 0 / 8

    uint4 ua0, ua1, ub0, ub1;
    auto gload = [&](int kt) {
        const uint4* pa = reinterpret_cast<const uint4*>(
            A  + (size_t)(brow + arow) * K + kt * 32 + akp * 2);
        const uint4* pb = reinterpret_cast<const uint4*>(
            BT + (size_t)(bcol + arow) * K + kt * 32 + akp * 2);
        ua0 = pa[0]; ua1 = pa[1];
        ub0 = pb[0]; ub1 = pb[1];
    };
    auto sstore = [&](int buf) {
        *reinterpret_cast<uint4*>(&As[buf][arow][akp])     = ua0;
        *reinterpret_cast<uint4*>(&As[buf][arow][akp + 4]) = ua1;
        *reinterpret_cast<uint4*>(&Bs[buf][arow][akp])     = ub0;
        *reinterpret_cast<uint4*>(&Bs[buf][arow][akp + 4]) = ub1;
    };
    auto compute = [&](int buf) {
        #pragma unroll
        for (int step = 0; step < 2; step++) {
            const int kpb = step << 3;
            unsigned af[2][4];
            #pragma unroll
            for (int mt = 0; mt < 2; mt++) {
                const int mr = (wm << 5) + (mt << 4) + g;
                af[mt][0] = As[buf][mr][kpb + tg];
                af[mt][1] = As[buf][mr + 8][kpb + tg];
                af[mt][2] = As[buf][mr][kpb + tg + 4];
                af[mt][3] = As[buf][mr + 8][kpb + tg + 4];
            }
            unsigned bfg[8][2];
            #pragma unroll
            for (int nt = 0; nt < 8; nt++) {
                const int nc = (wn << 6) + (nt << 3) + g;
                bfg[nt][0] = Bs[buf][nc][kpb + tg];
                bfg[nt][1] = Bs[buf][nc][kpb + tg + 4];
            }
            #pragma unroll
            for (int mt = 0; mt < 2; mt++)
                #pragma unroll
                for (int nt = 0; nt < 8; nt++)
                    mma16(acc[mt][nt], af[mt], bfg[nt]);
        }
    };

    gload(0); sstore(0); __syncthreads();
    const int nk = K >> 5;
    for (int kt = 0; kt < nk; kt++) {
        const int cur = kt & 1;
        if (kt + 1 < nk) gload(kt + 1);
        compute(cur);
        if (kt + 1 < nk) sstore(cur ^ 1);
        __syncthreads();
    }

    // epilogue
    #pragma unroll
    for (int mt = 0; mt < 2; mt++) {
        #pragma unroll
        for (int nt = 0; nt < 8; nt++) {
            const int r0 = brow + (wm << 5) + (mt << 4) + g;
            const int c0 = bcol + (wn << 6) + (nt << 3) + (tg << 1);
            const float b0 = bias[c0], b1 = bias[c0 + 1];
            const float v00 = acc[mt][nt][0] + b0, v01 = acc[mt][nt][1] + b1;
            const float v10 = acc[mt][nt][2] + b0, v11 = acc[mt][nt][3] + b1;
            if (mode == 0) {
                *reinterpret_cast<float2*>(&C[(size_t)r0 * N + c0])       = make_float2(v00, v01);
                *reinterpret_cast<float2*>(&C[(size_t)(r0 + 8) * N + c0]) = make_float2(v10, v11);
            } else if (mode == 1) {
                const int which = c0 >> 10;
                const int h = (c0 >> 6) & 15;
                const int d = c0 & 63;
                unsigned* dst = (which == 0) ? g_q : (which == 1) ? g_k : g_v;
                #pragma unroll
                for (int rr = 0; rr < 2; rr++) {
                    const int r = r0 + rr * 8;
                    const int b = r >> 11, s = r & 2047;
                    const size_t idx = (((size_t)((b * HH + h) * SS + s)) * HD + d) >> 1;
                    dst[idx] = rr ? pk(v10, v11) : pk(v00, v01);
                }
            } else {
                #pragma unroll
                for (int rr = 0; rr < 2; rr++) {
                    const int r = r0 + rr * 8;
                    const float ga = rr ? v10 : v00, gb = rr ? v11 : v01;
                    const size_t off = (size_t)r * N + c0;
                    const float2 ov = *reinterpret_cast<const float2*>(&fuse_o[off]);
                    const float2 xv = *reinterpret_cast<const float2*>(&fuse_x[off]);
                    float2 res;
                    res.x = ov.x / (1.f + ex2(-ga * 1.44269504f)) + xv.x;
                    res.y = ov.y / (1.f + ex2(-gb * 1.44269504f)) + xv.y;
                    *reinterpret_cast<float2*>(&C[off]) = res;
                }
            }
        }
    }
}

// ---------------- flash attention (bf16 MMA, online softmax) ----------------
// smem (u32 words): Qs[128][36], Ks[64][36], Vs[32][72], Pb[128][36],
//                   Ps f32[128][65], m/l/rs f32[128] each
#define QS_OFF 0
#define KS_OFF 4608
#define VS_OFF 6912
#define PB_OFF 9216
#define PS_OFF 13824
#define ST_OFF 22144
#define ATT_SMEM_BYTES (22528 * 4)
#define CEXP (0.125f * 1.44269504088896f)

__global__ __launch_bounds__(256) void attn_kernel()
{
    extern __shared__ unsigned smu[];
    unsigned* Qs = smu + QS_OFF;
    unsigned* Ks = smu + KS_OFF;
    unsigned* Vs = smu + VS_OFF;
    unsigned* Pb = smu + PB_OFF;
    float*    Ps = reinterpret_cast<float*>(smu + PS_OFF);
    float*    m_s = reinterpret_cast<float*>(smu + ST_OFF);
    float*    l_s = m_s + 128;
    float*    rs  = l_s + 128;

    const int tid  = threadIdx.x;
    const int warp = tid >> 5, lane = tid & 31;
    const int wm = warp >> 1, wn = warp & 1;
    const int g  = lane >> 2, tg = lane & 3;
    const int bh = blockIdx.y;
    const int q0 = blockIdx.x << 7;

    const unsigned* Qg = g_q + (size_t)bh * SS * 32;   // u32 words, 32/row
    const unsigned* Kg = g_k + (size_t)bh * SS * 32;
    const unsigned* Vg = g_v + (size_t)bh * SS * 32;

    // Q tile: 128 rows x 32 words
    {
        const int r = tid >> 1, kp0 = (tid & 1) << 4;
        const uint4* p = reinterpret_cast<const uint4*>(Qg + (size_t)(q0 + r) * 32 + kp0);
        #pragma unroll
        for (int j = 0; j < 4; j++)
            *reinterpret_cast<uint4*>(&Qs[r * 36 + kp0 + 4 * j]) = p[j];
    }
    if (tid < 128) { m_s[tid] = -1e30f; l_s[tid] = 0.f; }

    float oacc[2][4][4];
    #pragma unroll
    for (int i = 0; i < 2; i++)
        #pragma unroll
        for (int j = 0; j < 4; j++)
            #pragma unroll
            for (int k = 0; k < 4; k++) oacc[i][j][k] = 0.f;

    for (int kt = 0; kt < SS / 64; kt++) {
        __syncthreads();
        // K tile: 64 rows x 32 words
        {
            const int key = tid >> 2, wo = (tid & 3) << 3;
            const uint4* p = reinterpret_cast<const uint4*>(Kg + (size_t)(kt * 64 + key) * 32 + wo);
            *reinterpret_cast<uint4*>(&Ks[key * 36 + wo])     = p[0];
            *reinterpret_cast<uint4*>(&Ks[key * 36 + wo + 4]) = p[1];
        }
        // V tile: interleave key pairs -> Vs[kp][hd]
        {
            const int kp = tid >> 3, hd0 = (tid & 7) << 3;
            const uint4 a = *reinterpret_cast<const uint4*>(Vg + (size_t)(kt * 64 + 2 * kp) * 32 + (hd0 >> 1));
            const uint4 b = *reinterpret_cast<const uint4*>(Vg + (size_t)(kt * 64 + 2 * kp + 1) * 32 + (hd0 >> 1));
            uint4 o0, o1;
            o0.x = __byte_perm(a.x, b.x, 0x5410); o0.y = __byte_perm(a.x, b.x, 0x7632);
            o0.z = __byte_perm(a.y, b.y, 0x5410); o0.w = __byte_perm(a.y, b.y, 0x7632);
            o1.x = __byte_perm(a.z, b.z, 0x5410); o1.y = __byte_perm(a.z, b.z, 0x7632);
            o1.z = __byte_perm(a.w, b.w, 0x5410); o1.w = __byte_perm(a.w, b.w, 0x7632);
            *reinterpret_cast<uint4*>(&Vs[kp * 72 + hd0])     = o0;
            *reinterpret_cast<uint4*>(&Vs[kp * 72 + hd0 + 4]) = o1;
        }
        __syncthreads();

        // S = Q K^T  (128 x 64, k=64)
        float sacc[2][4][4];
        #pragma unroll
        for (int i = 0; i < 2; i++)
            #pragma unroll
            for (int j = 0; j < 4; j++)
                #pragma unroll
                for (int k = 0; k < 4; k++) sacc[i][j][k] = 0.f;
        #pragma unroll
        for (int step = 0; step < 4; step++) {
            const int kpb = step << 3;
            unsigned af[2][4];
            #pragma unroll
            for (int mt = 0; mt < 2; mt++) {
                const int mr = (wm << 5) + (mt << 4) + g;
                af[mt][0] = Qs[mr * 36 + kpb + tg];
                af[mt][1] = Qs[(mr + 8) * 36 + kpb + tg];
                af[mt][2] = Qs[mr * 36 + kpb + tg + 4];
                af[mt][3] = Qs[(mr + 8) * 36 + kpb + tg + 4];
            }
            unsigned bfg[4][2];
            #pragma unroll
            for (int nt = 0; nt < 4; nt++) {
                const int nc = (wn << 5) + (nt << 3) + g;
                bfg[nt][0] = Ks[nc * 36 + kpb + tg];
                bfg[nt][1] = Ks[nc * 36 + kpb + tg + 4];
            }
            #pragma unroll
            for (int mt = 0; mt < 2; mt++)
                #pragma unroll
                for (int nt = 0; nt < 4; nt++)
                    mma16(sacc[mt][nt], af[mt], bfg[nt]);
        }
        // raw scores -> Ps (f32)
        #pragma unroll
        for (int mt = 0; mt < 2; mt++)
            #pragma unroll
            for (int nt = 0; nt < 4; nt++) {
                const int r = (wm << 5) + (mt << 4) + g;
                const int c = (wn << 5) + (nt << 3) + (tg << 1);
                Ps[r * 65 + c]           = sacc[mt][nt][0];
                Ps[r * 65 + c + 1]       = sacc[mt][nt][1];
                Ps[(r + 8) * 65 + c]     = sacc[mt][nt][2];
                Ps[(r + 8) * 65 + c + 1] = sacc[mt][nt][3];
            }
        __syncthreads();

        // online softmax: 2 threads per row
        {
            const int row = tid >> 1, half = (tid & 1) << 5;
            const float mo = m_s[row];
            const float* pr = Ps + row * 65 + half;
            float mx = mo;
            #pragma unroll 8
            for (int j = 0; j < 32; j++) mx = fmaxf(mx, pr[j]);
            mx = fmaxf(mx, __shfl_xor_sync(0xFFFFFFFFu, mx, 1));
            float sum = 0.f;
            #pragma unroll
            for (int j = 0; j < 32; j += 2) {
                const float p0 = ex2((pr[j]     - mx) * CEXP);
                const float p1 = ex2((pr[j + 1] - mx) * CEXP);
                sum += p0 + p1;
                Pb[row * 36 + (half >> 1) + (j >> 1)] = pk(p0, p1);
            }
            sum += __shfl_xor_sync(0xFFFFFFFFu, sum, 1);
            if ((tid & 1) == 0) {
                const float f = ex2((mo - mx) * CEXP);
                l_s[row] = l_s[row] * f + sum;
                m_s[row] = mx;
                rs[row]  = f;
            }
        }
        __syncthreads();

        // rescale + O += P V
        #pragma unroll
        for (int mt = 0; mt < 2; mt++) {
            const int r = (wm << 5) + (mt << 4) + g;
            const float f0 = rs[r], f1 = rs[r + 8];
            #pragma unroll
            for (int nt = 0; nt < 4; nt++) {
                oacc[mt][nt][0] *= f0; oacc[mt][nt][1] *= f0;
                oacc[mt][nt][2] *= f1; oacc[mt][nt][3] *= f1;
            }
        }
        #pragma unroll
        for (int step = 0; step < 4; step++) {
            const int kpb = step << 3;
            unsigned af[2][4];
            #pragma unroll
            for (int mt = 0; mt < 2; mt++) {
                const int mr = (wm << 5) + (mt << 4) + g;
                af[mt][0] = Pb[mr * 36 + kpb + tg];
                af[mt][1] = Pb[(mr + 8) * 36 + kpb + tg];
                af[mt][2] = Pb[mr * 36 + kpb + tg + 4];
                af[mt][3] = Pb[(mr + 8) * 36 + kpb + tg + 4];
            }
            unsigned bfg[4][2];
            #pragma unroll
            for (int nt = 0; nt < 4; nt++) {
                const int nc = (wn << 5) + (nt << 3) + g;
                bfg[nt][0] = Vs[(kpb + tg) * 72 + nc];
                bfg[nt][1] = Vs[(kpb + tg + 4) * 72 + nc];
            }
            #pragma unroll
            for (int mt = 0; mt < 2; mt++)
                #pragma unroll
                for (int nt = 0; nt < 4; nt++)
                    mma16(oacc[mt][nt], af[mt], bfg[nt]);
        }
    }

    // normalize + write ctx bf16 in [B,S,D]
    const int b = bh >> 4, h = bh & 15;
    #pragma unroll
    for (int mt = 0; mt < 2; mt++) {
        const int r = (wm << 5) + (mt << 4) + g;
        const float inv0 = 1.f / l_s[r];
        const float inv1 = 1.f / l_s[r + 8];
        #pragma unroll
        for (int nt = 0; nt < 4; nt++) {
            const int c = (wn << 5) + (nt << 3) + (tg << 1);
            const size_t w0 = (((size_t)(b * SS + q0 + r))     * DD + h * HD + c) >> 1;
            const size_t w1 = (((size_t)(b * SS + q0 + r + 8)) * DD + h * HD + c) >> 1;
            g_ctx[w0] = pk(oacc[mt][nt][0] * inv0, oacc[mt][nt][1] * inv0);
            g_ctx[w1] = pk(oacc[mt][nt][2] * inv1, oacc[mt][nt][3] * inv1);
        }
    }
}

// ---------------- launch ----------------
extern "C" void kernel_launch(void* const* d_in, const int* in_sizes, int n_in,
                              void* d_out, int out_size)
{
    const float* x      = (const float*)d_in[0];
    const float* gamma  = (const float*)d_in[1];
    const float* beta   = (const float*)d_in[2];
    const float* w_qkv  = (const float*)d_in[3];
    const float* b_qkv  = (const float*)d_in[4];
    const float* w_out  = (const float*)d_in[5];
    const float* b_out  = (const float*)d_in[6];
    const float* w_gate = (const float*)d_in[7];
    const float* b_gate = (const float*)d_in[8];
    float* out = (float*)d_out;

    void *p_xn, *p_ctx, *p_outb, *p_wq, *p_wo, *p_wg;
    cudaGetSymbolAddress(&p_xn,   g_xn);
    cudaGetSymbolAddress(&p_ctx,  g_ctx);
    cudaGetSymbolAddress(&p_outb, g_outb);
    cudaGetSymbolAddress(&p_wq,   g_wqT);
    cudaGetSymbolAddress(&p_wo,   g_woT);
    cudaGetSymbolAddress(&p_wg,   g_wgT);

    cudaFuncSetAttribute(attn_kernel,
                         cudaFuncAttributeMaxDynamicSharedMemorySize,
                         ATT_SMEM_BYTES);

    ln_kernel<<<MROWS, 256>>>(x, gamma, beta);

    dim3 tb(32, 8);
    wconv<<<dim3(3 * DD / 32, DD / 32), tb>>>(w_qkv,  (__nv_bfloat16*)p_wq, DD, 3 * DD);
    wconv<<<dim3(DD / 32,     DD / 32), tb>>>(w_out,  (__nv_bfloat16*)p_wo, DD, DD);
    wconv<<<dim3(DD / 32,     DD / 32), tb>>>(w_gate, (__nv_bfloat16*)p_wg, DD, DD);

    // QKV: [4096,1024] x [3072,1024]^T -> scatter bf16 q/k/v
    gemm_bf16<<<dim3(3 * DD / 128, MROWS / 128), 256>>>(
        (const __nv_bfloat16*)p_xn, (const __nv_bfloat16*)p_wq, b_qkv,
        nullptr, nullptr, nullptr, MROWS, 3 * DD, DD, 1);

    attn_kernel<<<dim3(SS / 128, BB * HH), 256, ATT_SMEM_BYTES>>>();

    // out proj -> f32 scratch
    gemm_bf16<<<dim3(DD / 128, MROWS / 128), 256>>>(
        (const __nv_bfloat16*)p_ctx, (const __nv_bfloat16*)p_wo, b_out,
        (float*)p_outb, nullptr, nullptr, MROWS, DD, DD, 0);

    // gate proj fused with out*sigmoid(gate)+x -> d_out
    gemm_bf16<<<dim3(DD / 128, MROWS / 128), 256>>>(
        (const __nv_bfloat16*)p_xn, (const __nv_bfloat16*)p_wg, b_gate,
        out, (const float*)p_outb, x, MROWS, DD, DD, 2);
}

// round 3
// speedup vs baseline: 1.8695x; 1.3099x over previous
#include <cuda_runtime.h>
#include <cuda_bf16.h>
#include <math.h>

#define BB 2
#define SS 2048
#define DD 1024
#define HH 16
#define HD 64
#define MROWS (BB*SS)          // 4096

// ---------------- scratch (device globals; no allocation) ----------------
__device__ __align__(16) unsigned g_xn  [MROWS*DD/2];       // bf16 [M][D]
__device__ __align__(16) unsigned g_q   [BB*HH*SS*HD/2];    // bf16 [B,H,S,HD]
__device__ __align__(16) unsigned g_k   [BB*HH*SS*HD/2];
__device__ __align__(16) unsigned g_v   [BB*HH*SS*HD/2];
__device__ __align__(16) unsigned g_ctx [MROWS*DD/2];       // bf16 [B,S,D]
__device__ __align__(16) float    g_outb[MROWS*DD];         // f32
__device__ __align__(16) unsigned g_wqT [3*DD*DD/2];        // bf16 [3D][D] (W^T)
__device__ __align__(16) unsigned g_woT [DD*DD/2];          // bf16 [D][D]
__device__ __align__(16) unsigned g_wgT [DD*DD/2];

// ---------------- helpers ----------------
__device__ __forceinline__ float ex2(float x) {
    float y; asm("ex2.approx.ftz.f32 %0, %1;" : "=f"(y) : "f"(x)); return y;
}
// pack (lo, hi) -> bf16x2 ; PTX cvt packs first source into the HIGH half
__device__ __forceinline__ unsigned pk(float lo, float hi) {
    unsigned r; asm("cvt.rn.bf16x2.f32 %0, %1, %2;" : "=r"(r) : "f"(hi), "f"(lo));
    return r;
}
__device__ __forceinline__ void mma16(float* d, const unsigned* a, const unsigned* b) {
    asm volatile(
        "mma.sync.aligned.m16n8k16.row.col.f32.bf16.bf16.f32 "
        "{%0,%1,%2,%3}, {%4,%5,%6,%7}, {%8,%9}, {%0,%1,%2,%3};"
        : "+f"(d[0]), "+f"(d[1]), "+f"(d[2]), "+f"(d[3])
        : "r"(a[0]), "r"(a[1]), "r"(a[2]), "r"(a[3]),
          "r"(b[0]), "r"(b[1]));
}
__device__ __forceinline__ void ldsm4(unsigned* r, const unsigned* p) {
    unsigned addr = (unsigned)__cvta_generic_to_shared(p);
    asm volatile("ldmatrix.sync.aligned.m8n8.x4.shared.b16 {%0,%1,%2,%3}, [%4];"
                 : "=r"(r[0]), "=r"(r[1]), "=r"(r[2]), "=r"(r[3]) : "r"(addr));
}

// ---------------- LayerNorm -> bf16 ----------------
__global__ __launch_bounds__(256) void ln_kernel(
    const float* __restrict__ x, const float* __restrict__ gamma,
    const float* __restrict__ beta)
{
    const int row = blockIdx.x;
    const int t = threadIdx.x;
    const float4 v = reinterpret_cast<const float4*>(x + (size_t)row * DD)[t];
    float s  = v.x + v.y + v.z + v.w;
    float s2 = v.x*v.x + v.y*v.y + v.z*v.z + v.w*v.w;
    #pragma unroll
    for (int o = 16; o > 0; o >>= 1) {
        s  += __shfl_xor_sync(0xFFFFFFFFu, s,  o);
        s2 += __shfl_xor_sync(0xFFFFFFFFu, s2, o);
    }
    __shared__ float ws[8], ws2[8];
    if ((t & 31) == 0) { ws[t >> 5] = s; ws2[t >> 5] = s2; }
    __syncthreads();
    float st = 0.f, st2 = 0.f;
    #pragma unroll
    for (int i = 0; i < 8; i++) { st += ws[i]; st2 += ws2[i]; }
    const float mu  = st * (1.f / DD);
    const float var = st2 * (1.f / DD) - mu * mu;
    const float inv = rsqrtf(var + 1e-5f);
    const float4 gm = reinterpret_cast<const float4*>(gamma)[t];
    const float4 bt = reinterpret_cast<const float4*>(beta)[t];
    uint2 o;
    o.x = pk((v.x - mu) * inv * gm.x + bt.x, (v.y - mu) * inv * gm.y + bt.y);
    o.y = pk((v.z - mu) * inv * gm.z + bt.z, (v.w - mu) * inv * gm.w + bt.w);
    reinterpret_cast<uint2*>(g_xn)[row * 256 + t] = o;
}

// ---------------- weight transpose + fp32->bf16 ----------------
__global__ __launch_bounds__(256) void wconv(
    const float* __restrict__ src, __nv_bfloat16* __restrict__ dst, int K, int N)
{
    __shared__ float s[32][33];
    const int tx = threadIdx.x, ty = threadIdx.y;
    const int n0 = blockIdx.x << 5, k0 = blockIdx.y << 5;
    #pragma unroll
    for (int i = 0; i < 4; i++)
        s[ty + 8*i][tx] = src[(size_t)(k0 + ty + 8*i) * N + n0 + tx];
    __syncthreads();
    #pragma unroll
    for (int i = 0; i < 4; i++)
        dst[(size_t)(n0 + ty + 8*i) * K + k0 + tx] = __float2bfloat16(s[tx][ty + 8*i]);
}

// ---------------- bf16 tensor GEMM: C = A[MxK] * BT[NxK]^T + bias ----------------
// mode 0: f32 store to C. mode 1: scatter bf16 into g_q/g_k/g_v.
// mode 2: fused gate: C[r,c] = fuse_o[r,c]*sigmoid(acc+bias) + fuse_x[r,c]
__global__ __launch_bounds__(256) void gemm_bf16(
    const __nv_bfloat16* __restrict__ A, const __nv_bfloat16* __restrict__ BT,
    const float* __restrict__ bias, float* __restrict__ C,
    const float* __restrict__ fuse_o, const float* __restrict__ fuse_x,
    int M, int N, int K, int mode)
{
    __shared__ unsigned As[2][128][20];   // [m][kp]  kp = k/2
    __shared__ unsigned Bs[2][128][20];   // [n][kp]

    const int tid  = threadIdx.x;
    const int warp = tid >> 5, lane = tid & 31;
    const int wm = warp >> 1, wn = warp & 1;
    const int g  = lane >> 2, tg = lane & 3;
    const int lm = lane >> 3, lr = lane & 7;   // ldmatrix: matrix id, row
    const int brow = blockIdx.y << 7, bcol = blockIdx.x << 7;

    float acc[2][8][4];
    #pragma unroll
    for (int i = 0; i < 2; i++)
        #pragma unroll
        for (int j = 0; j < 8; j++)
            #pragma unroll
            for (int k = 0; k < 4; k++) acc[i][j][k] = 0.f;

    const int arow = tid >> 1;            // tile row (both A and BT)
    const int akp  = (tid & 1) << 3;      // kp offset 0 / 8

    uint4 ua0, ua1, ub0, ub1;
    auto gload = [&](int kt) {
        const uint4* pa = reinterpret_cast<const uint4*>(
            A  + (size_t)(brow + arow) * K + kt * 32 + akp * 2);
        const uint4* pb = reinterpret_cast<const uint4*>(
            BT + (size_t)(bcol + arow) * K + kt * 32 + akp * 2);
        ua0 = pa[0]; ua1 = pa[1];
        ub0 = pb[0]; ub1 = pb[1];
    };
    auto sstore = [&](int buf) {
        *reinterpret_cast<uint4*>(&As[buf][arow][akp])     = ua0;
        *reinterpret_cast<uint4*>(&As[buf][arow][akp + 4]) = ua1;
        *reinterpret_cast<uint4*>(&Bs[buf][arow][akp])     = ub0;
        *reinterpret_cast<uint4*>(&Bs[buf][arow][akp + 4]) = ub1;
    };
    auto compute = [&](int buf) {
        #pragma unroll
        for (int step = 0; step < 2; step++) {
            const int kpb = step << 3;
            const int lcol = kpb + ((lm >> 1) << 2);
            unsigned af[2][4];
            #pragma unroll
            for (int mt = 0; mt < 2; mt++) {
                const int row = (wm << 5) + (mt << 4) + ((lm & 1) << 3) + lr;
                ldsm4(af[mt], &As[buf][row][lcol]);
            }
            unsigned bfg[8][2];
            #pragma unroll
            for (int np = 0; np < 4; np++) {
                const int row = (wn << 6) + (np << 4) + ((lm & 1) << 3) + lr;
                unsigned t[4];
                ldsm4(t, &Bs[buf][row][lcol]);
                bfg[np*2][0]   = t[0]; bfg[np*2+1][0] = t[1];
                bfg[np*2][1]   = t[2]; bfg[np*2+1][1] = t[3];
            }
            #pragma unroll
            for (int mt = 0; mt < 2; mt++)
                #pragma unroll
                for (int nt = 0; nt < 8; nt++)
                    mma16(acc[mt][nt], af[mt], bfg[nt]);
        }
    };

    gload(0); sstore(0); __syncthreads();
    const int nk = K >> 5;
    for (int kt = 0; kt < nk; kt++) {
        const int cur = kt & 1;
        if (kt + 1 < nk) gload(kt + 1);
        compute(cur);
        if (kt + 1 < nk) sstore(cur ^ 1);
        __syncthreads();
    }

    // epilogue
    #pragma unroll
    for (int mt = 0; mt < 2; mt++) {
        #pragma unroll
        for (int nt = 0; nt < 8; nt++) {
            const int r0 = brow + (wm << 5) + (mt << 4) + g;
            const int c0 = bcol + (wn << 6) + (nt << 3) + (tg << 1);
            const float b0 = bias[c0], b1 = bias[c0 + 1];
            const float v00 = acc[mt][nt][0] + b0, v01 = acc[mt][nt][1] + b1;
            const float v10 = acc[mt][nt][2] + b0, v11 = acc[mt][nt][3] + b1;
            if (mode == 0) {
                *reinterpret_cast<float2*>(&C[(size_t)r0 * N + c0])       = make_float2(v00, v01);
                *reinterpret_cast<float2*>(&C[(size_t)(r0 + 8) * N + c0]) = make_float2(v10, v11);
            } else if (mode == 1) {
                const int which = c0 >> 10;
                const int h = (c0 >> 6) & 15;
                const int d = c0 & 63;
                unsigned* dst = (which == 0) ? g_q : (which == 1) ? g_k : g_v;
                #pragma unroll
                for (int rr = 0; rr < 2; rr++) {
                    const int r = r0 + rr * 8;
                    const int b = r >> 11, s = r & 2047;
                    const size_t idx = (((size_t)((b * HH + h) * SS + s)) * HD + d) >> 1;
                    dst[idx] = rr ? pk(v10, v11) : pk(v00, v01);
                }
            } else {
                #pragma unroll
                for (int rr = 0; rr < 2; rr++) {
                    const int r = r0 + rr * 8;
                    const float ga = rr ? v10 : v00, gb = rr ? v11 : v01;
                    const size_t off = (size_t)r * N + c0;
                    const float2 ov = *reinterpret_cast<const float2*>(&fuse_o[off]);
                    const float2 xv = *reinterpret_cast<const float2*>(&fuse_x[off]);
                    float2 res;
                    res.x = ov.x / (1.f + ex2(-ga * 1.44269504f)) + xv.x;
                    res.y = ov.y / (1.f + ex2(-gb * 1.44269504f)) + xv.y;
                    *reinterpret_cast<float2*>(&C[off]) = res;
                }
            }
        }
    }
}

// ---------------- flash attention: register softmax, Q-in-regs ----------------
#define CEXP (0.125f * 1.44269504088896f)
#define NT (SS / 64)

__global__ __launch_bounds__(256) void attn_kernel()
{
    __shared__ unsigned Ks[64][36];   // [key][hd word]
    __shared__ unsigned Vs[32][72];   // [key pair][hd]

    const int tid  = threadIdx.x;
    const int warp = tid >> 5, lane = tid & 31;
    const int g  = lane >> 2, tg = lane & 3;
    const int lm = lane >> 3, lr = lane & 7;
    const int bh = blockIdx.y;
    const int q0 = blockIdx.x << 7;
    const int mr0 = warp << 4;             // 16 q-rows per warp

    const unsigned* Qg = g_q + (size_t)bh * SS * 32;   // 32 words/row
    const unsigned* Kg = g_k + (size_t)bh * SS * 32;
    const unsigned* Vg = g_v + (size_t)bh * SS * 32;

    // ---- Q fragments in registers (constant over all kv tiles) ----
    unsigned qf[4][4];
    {
        const unsigned* r0p = Qg + (size_t)(q0 + mr0 + g) * 32;
        const unsigned* r1p = Qg + (size_t)(q0 + mr0 + g + 8) * 32;
        #pragma unroll
        for (int kc = 0; kc < 4; kc++) {
            qf[kc][0] = r0p[kc*8 + tg];
            qf[kc][1] = r1p[kc*8 + tg];
            qf[kc][2] = r0p[kc*8 + tg + 4];
            qf[kc][3] = r1p[kc*8 + tg + 4];
        }
    }

    // softmax state (rows g and g+8), replicated across quad
    float m0 = -1e30f, m1 = -1e30f, l0 = 0.f, l1 = 0.f;
    float oacc[8][4];
    #pragma unroll
    for (int j = 0; j < 8; j++)
        #pragma unroll
        for (int k = 0; k < 4; k++) oacc[j][k] = 0.f;

    // K/V global-load indices
    const int kkey = tid >> 2, kwo = (tid & 3) << 3;     // K: row, word offset
    const int vkp  = tid >> 3, vhd = (tid & 7) << 3;     // V: key pair, hd base

    uint4 uk0, uk1, va, vb;
    auto gload = [&](int kt) {
        const uint4* pk_ = reinterpret_cast<const uint4*>(
            Kg + (size_t)(kt * 64 + kkey) * 32 + kwo);
        uk0 = pk_[0]; uk1 = pk_[1];
        va = *reinterpret_cast<const uint4*>(Vg + (size_t)(kt * 64 + 2*vkp)     * 32 + (vhd >> 1));
        vb = *reinterpret_cast<const uint4*>(Vg + (size_t)(kt * 64 + 2*vkp + 1) * 32 + (vhd >> 1));
    };

    gload(0);
    for (int kt = 0; kt < NT; kt++) {
        // store staged tile
        *reinterpret_cast<uint4*>(&Ks[kkey][kwo])     = uk0;
        *reinterpret_cast<uint4*>(&Ks[kkey][kwo + 4]) = uk1;
        {
            uint4 o0, o1;
            o0.x = __byte_perm(va.x, vb.x, 0x5410); o0.y = __byte_perm(va.x, vb.x, 0x7632);
            o0.z = __byte_perm(va.y, vb.y, 0x5410); o0.w = __byte_perm(va.y, vb.y, 0x7632);
            o1.x = __byte_perm(va.z, vb.z, 0x5410); o1.y = __byte_perm(va.z, vb.z, 0x7632);
            o1.z = __byte_perm(va.w, vb.w, 0x5410); o1.w = __byte_perm(va.w, vb.w, 0x7632);
            *reinterpret_cast<uint4*>(&Vs[vkp][vhd])     = o0;
            *reinterpret_cast<uint4*>(&Vs[vkp][vhd + 4]) = o1;
        }
        __syncthreads();
        if (kt + 1 < NT) gload(kt + 1);   // prefetch overlaps compute

        // ---- S = Q K^T : 16 rows x 64 keys, k = 64 ----
        float sacc[8][4];
        #pragma unroll
        for (int j = 0; j < 8; j++)
            #pragma unroll
            for (int k = 0; k < 4; k++) sacc[j][k] = 0.f;

        #pragma unroll
        for (int kc = 0; kc < 4; kc++) {
            const int lcol = kc*8 + ((lm >> 1) << 2);
            #pragma unroll
            for (int np = 0; np < 4; np++) {
                unsigned t[4];
                ldsm4(t, &Ks[np*16 + ((lm & 1) << 3) + lr][lcol]);
                unsigned b0[2] = { t[0], t[2] };
                unsigned b1[2] = { t[1], t[3] };
                mma16(sacc[np*2],     qf[kc], b0);
                mma16(sacc[np*2 + 1], qf[kc], b1);
            }
        }

        // ---- register online softmax ----
        float mx0 = sacc[0][0], mx1 = sacc[0][2];
        #pragma unroll
        for (int nt = 0; nt < 8; nt++) {
            mx0 = fmaxf(mx0, fmaxf(sacc[nt][0], sacc[nt][1]));
            mx1 = fmaxf(mx1, fmaxf(sacc[nt][2], sacc[nt][3]));
        }
        mx0 = fmaxf(mx0, __shfl_xor_sync(0xFFFFFFFFu, mx0, 1));
        mx0 = fmaxf(mx0, __shfl_xor_sync(0xFFFFFFFFu, mx0, 2));
        mx1 = fmaxf(mx1, __shfl_xor_sync(0xFFFFFFFFu, mx1, 1));
        mx1 = fmaxf(mx1, __shfl_xor_sync(0xFFFFFFFFu, mx1, 2));
        const float M0 = fmaxf(m0, mx0), M1 = fmaxf(m1, mx1);
        const float f0 = ex2((m0 - M0) * CEXP), f1 = ex2((m1 - M1) * CEXP);
        m0 = M0; m1 = M1;

        float sum0 = 0.f, sum1 = 0.f;
        #pragma unroll
        for (int nt = 0; nt < 8; nt++) {
            const float p0 = ex2((sacc[nt][0] - M0) * CEXP);
            const float p1 = ex2((sacc[nt][1] - M0) * CEXP);
            const float p2 = ex2((sacc[nt][2] - M1) * CEXP);
            const float p3 = ex2((sacc[nt][3] - M1) * CEXP);
            sacc[nt][0] = p0; sacc[nt][1] = p1; sacc[nt][2] = p2; sacc[nt][3] = p3;
            sum0 += p0 + p1; sum1 += p2 + p3;
        }
        sum0 += __shfl_xor_sync(0xFFFFFFFFu, sum0, 1);
        sum0 += __shfl_xor_sync(0xFFFFFFFFu, sum0, 2);
        sum1 += __shfl_xor_sync(0xFFFFFFFFu, sum1, 1);
        sum1 += __shfl_xor_sync(0xFFFFFFFFu, sum1, 2);
        l0 = l0 * f0 + sum0;
        l1 = l1 * f1 + sum1;

        // rescale O
        #pragma unroll
        for (int nt = 0; nt < 8; nt++) {
            oacc[nt][0] *= f0; oacc[nt][1] *= f0;
            oacc[nt][2] *= f1; oacc[nt][3] *= f1;
        }

        // pack P fragments straight from S registers
        unsigned pf[4][4];
        #pragma unroll
        for (int kc = 0; kc < 4; kc++) {
            pf[kc][0] = pk(sacc[2*kc][0],     sacc[2*kc][1]);
            pf[kc][1] = pk(sacc[2*kc][2],     sacc[2*kc][3]);
            pf[kc][2] = pk(sacc[2*kc + 1][0], sacc[2*kc + 1][1]);
            pf[kc][3] = pk(sacc[2*kc + 1][2], sacc[2*kc + 1][3]);
        }

        // ---- O += P V ----
        #pragma unroll
        for (int kc = 0; kc < 4; kc++) {
            #pragma unroll
            for (int nt = 0; nt < 8; nt++) {
                unsigned b[2] = { Vs[kc*8 + tg][nt*8 + g], Vs[kc*8 + tg + 4][nt*8 + g] };
                mma16(oacc[nt], pf[kc], b);
            }
        }
        __syncthreads();
    }

    // ---- normalize + write ctx bf16 in [B,S,D] ----
    const int b = bh >> 4, h = bh & 15;
    const float inv0 = 1.f / l0, inv1 = 1.f / l1;
    const size_t row0 = (size_t)(b * SS + q0 + mr0 + g)     * (DD/2) + h * (HD/2);
    const size_t row1 = (size_t)(b * SS + q0 + mr0 + g + 8) * (DD/2) + h * (HD/2);
    #pragma unroll
    for (int nt = 0; nt < 8; nt++) {
        g_ctx[row0 + nt*4 + tg] = pk(oacc[nt][0] * inv0, oacc[nt][1] * inv0);
        g_ctx[row1 + nt*4 + tg] = pk(oacc[nt][2] * inv1, oacc[nt][3] * inv1);
    }
}

// ---------------- launch ----------------
extern "C" void kernel_launch(void* const* d_in, const int* in_sizes, int n_in,
                              void* d_out, int out_size)
{
    const float* x      = (const float*)d_in[0];
    const float* gamma  = (const float*)d_in[1];
    const float* beta   = (const float*)d_in[2];
    const float* w_qkv  = (const float*)d_in[3];
    const float* b_qkv  = (const float*)d_in[4];
    const float* w_out  = (const float*)d_in[5];
    const float* b_out  = (const float*)d_in[6];
    const float* w_gate = (const float*)d_in[7];
    const float* b_gate = (const float*)d_in[8];
    float* out = (float*)d_out;

    void *p_xn, *p_ctx, *p_outb, *p_wq, *p_wo, *p_wg;
    cudaGetSymbolAddress(&p_xn,   g_xn);
    cudaGetSymbolAddress(&p_ctx,  g_ctx);
    cudaGetSymbolAddress(&p_outb, g_outb);
    cudaGetSymbolAddress(&p_wq,   g_wqT);
    cudaGetSymbolAddress(&p_wo,   g_woT);
    cudaGetSymbolAddress(&p_wg,   g_wgT);

    ln_kernel<<<MROWS, 256>>>(x, gamma, beta);

    dim3 tb(32, 8);
    wconv<<<dim3(3 * DD / 32, DD / 32), tb>>>(w_qkv,  (__nv_bfloat16*)p_wq, DD, 3 * DD);
    wconv<<<dim3(DD / 32,     DD / 32), tb>>>(w_out,  (__nv_bfloat16*)p_wo, DD, DD);
    wconv<<<dim3(DD / 32,     DD / 32), tb>>>(w_gate, (__nv_bfloat16*)p_wg, DD, DD);

    // QKV: [4096,1024] x [3072,1024]^T -> scatter bf16 q/k/v
    gemm_bf16<<<dim3(3 * DD / 128, MROWS / 128), 256>>>(
        (const __nv_bfloat16*)p_xn, (const __nv_bfloat16*)p_wq, b_qkv,
        nullptr, nullptr, nullptr, MROWS, 3 * DD, DD, 1);

    attn_kernel<<<dim3(SS / 128, BB * HH), 256>>>();

    // out proj -> f32 scratch
    gemm_bf16<<<dim3(DD / 128, MROWS / 128), 256>>>(
        (const __nv_bfloat16*)p_ctx, (const __nv_bfloat16*)p_wo, b_out,
        (float*)p_outb, nullptr, nullptr, MROWS, DD, DD, 0);

    // gate proj fused with out*sigmoid(gate)+x -> d_out
    gemm_bf16<<<dim3(DD / 128, MROWS / 128), 256>>>(
        (const __nv_bfloat16*)p_xn, (const __nv_bfloat16*)p_wg, b_gate,
        out, (const float*)p_outb, x, MROWS, DD, DD, 2);
}

// round 4
// speedup vs baseline: 2.4064x; 1.2872x over previous
#include <cuda_runtime.h>
#include <cuda_bf16.h>
#include <math.h>

#define BB 2
#define SS 2048
#define DD 1024
#define HH 16
#define HD 64
#define MROWS (BB*SS)          // 4096

// ---------------- scratch (device globals; no allocation) ----------------
__device__ __align__(16) unsigned g_xn  [MROWS*DD/2];       // bf16 [M][D]
__device__ __align__(16) unsigned g_q   [BB*HH*SS*HD/2];    // bf16 [B,H,S,HD]
__device__ __align__(16) unsigned g_k   [BB*HH*SS*HD/2];
__device__ __align__(16) unsigned g_v   [BB*HH*SS*HD/2];
__device__ __align__(16) unsigned g_ctx [MROWS*DD/2];       // bf16 [B,S,D]
__device__ __align__(16) float    g_outb[MROWS*DD];         // f32
__device__ __align__(16) unsigned g_wqT [3*DD*DD/2];        // bf16 [3D][D] (W^T)
__device__ __align__(16) unsigned g_woT [DD*DD/2];          // bf16 [D][D]
__device__ __align__(16) unsigned g_wgT [DD*DD/2];

// ---------------- helpers ----------------
__device__ __forceinline__ float ex2(float x) {
    float y; asm("ex2.approx.ftz.f32 %0, %1;" : "=f"(y) : "f"(x)); return y;
}
__device__ __forceinline__ unsigned pk(float lo, float hi) {
    unsigned r; asm("cvt.rn.bf16x2.f32 %0, %1, %2;" : "=r"(r) : "f"(hi), "f"(lo));
    return r;
}
__device__ __forceinline__ void mma16(float* d, const unsigned* a, const unsigned* b) {
    asm volatile(
        "mma.sync.aligned.m16n8k16.row.col.f32.bf16.bf16.f32 "
        "{%0,%1,%2,%3}, {%4,%5,%6,%7}, {%8,%9}, {%0,%1,%2,%3};"
        : "+f"(d[0]), "+f"(d[1]), "+f"(d[2]), "+f"(d[3])
        : "r"(a[0]), "r"(a[1]), "r"(a[2]), "r"(a[3]),
          "r"(b[0]), "r"(b[1]));
}
__device__ __forceinline__ void ldsm4(unsigned* r, const unsigned* p) {
    unsigned addr = (unsigned)__cvta_generic_to_shared(p);
    asm volatile("ldmatrix.sync.aligned.m8n8.x4.shared.b16 {%0,%1,%2,%3}, [%4];"
                 : "=r"(r[0]), "=r"(r[1]), "=r"(r[2]), "=r"(r[3]) : "r"(addr));
}
__device__ __forceinline__ void ldsm4t(unsigned* r, const unsigned* p) {
    unsigned addr = (unsigned)__cvta_generic_to_shared(p);
    asm volatile("ldmatrix.sync.aligned.m8n8.x4.trans.shared.b16 {%0,%1,%2,%3}, [%4];"
                 : "=r"(r[0]), "=r"(r[1]), "=r"(r[2]), "=r"(r[3]) : "r"(addr));
}
__device__ __forceinline__ void cpa(void* s, const void* g) {
    unsigned sa = (unsigned)__cvta_generic_to_shared(s);
    asm volatile("cp.async.cg.shared.global [%0], [%1], 16;" :: "r"(sa), "l"(g));
}
#define CP_COMMIT() asm volatile("cp.async.commit_group;" ::: "memory")
#define CP_WAIT(n)  asm volatile("cp.async.wait_group %0;" :: "n"(n) : "memory")

// ---------------- LayerNorm -> bf16 ----------------
__global__ __launch_bounds__(256) void ln_kernel(
    const float* __restrict__ x, const float* __restrict__ gamma,
    const float* __restrict__ beta)
{
    const int row = blockIdx.x;
    const int t = threadIdx.x;
    const float4 v = reinterpret_cast<const float4*>(x + (size_t)row * DD)[t];
    float s  = v.x + v.y + v.z + v.w;
    float s2 = v.x*v.x + v.y*v.y + v.z*v.z + v.w*v.w;
    #pragma unroll
    for (int o = 16; o > 0; o >>= 1) {
        s  += __shfl_xor_sync(0xFFFFFFFFu, s,  o);
        s2 += __shfl_xor_sync(0xFFFFFFFFu, s2, o);
    }
    __shared__ float ws[8], ws2[8];
    if ((t & 31) == 0) { ws[t >> 5] = s; ws2[t >> 5] = s2; }
    __syncthreads();
    float st = 0.f, st2 = 0.f;
    #pragma unroll
    for (int i = 0; i < 8; i++) { st += ws[i]; st2 += ws2[i]; }
    const float mu  = st * (1.f / DD);
    const float var = st2 * (1.f / DD) - mu * mu;
    const float inv = rsqrtf(var + 1e-5f);
    const float4 gm = reinterpret_cast<const float4*>(gamma)[t];
    const float4 bt = reinterpret_cast<const float4*>(beta)[t];
    uint2 o;
    o.x = pk((v.x - mu) * inv * gm.x + bt.x, (v.y - mu) * inv * gm.y + bt.y);
    o.y = pk((v.z - mu) * inv * gm.z + bt.z, (v.w - mu) * inv * gm.w + bt.w);
    reinterpret_cast<uint2*>(g_xn)[row * 256 + t] = o;
}

// ---------------- all weight transposes + fp32->bf16 in one launch ----------------
__global__ __launch_bounds__(256) void wconv_all(
    const float* __restrict__ w_qkv, const float* __restrict__ w_out,
    const float* __restrict__ w_gate)
{
    __shared__ float s[32][33];
    int bx = blockIdx.x;
    const float* src; unsigned* dstw; int N;
    if (bx < 96)       { src = w_qkv;  dstw = g_wqT; N = 3 * DD; }
    else if (bx < 128) { src = w_out;  dstw = g_woT; N = DD; bx -= 96; }
    else               { src = w_gate; dstw = g_wgT; N = DD; bx -= 128; }
    __nv_bfloat16* dst = reinterpret_cast<__nv_bfloat16*>(dstw);
    const int tx = threadIdx.x, ty = threadIdx.y;
    const int n0 = bx << 5, k0 = blockIdx.y << 5;
    #pragma unroll
    for (int i = 0; i < 4; i++)
        s[ty + 8*i][tx] = src[(size_t)(k0 + ty + 8*i) * N + n0 + tx];
    __syncthreads();
    #pragma unroll
    for (int i = 0; i < 4; i++)
        dst[(size_t)(n0 + ty + 8*i) * DD + k0 + tx] = __float2bfloat16(s[tx][ty + 8*i]);
}

// ---------------- bf16 tensor GEMM, cp.async 3-stage: C = A * BT^T + bias ----------
// mode 0: f32 store. mode 1: scatter bf16 q/k/v. mode 2: fused out*sigmoid(gate)+x.
#define GS 2560                     // words per stage per operand: 128*20
#define GEMM_SMEM_BYTES (6 * GS * 4)

__global__ __launch_bounds__(256, 2) void gemm_bf16(
    const __nv_bfloat16* __restrict__ A, const __nv_bfloat16* __restrict__ BT,
    const float* __restrict__ bias, float* __restrict__ C,
    const float* __restrict__ fuse_o, const float* __restrict__ fuse_x,
    int M, int N, int K, int mode)
{
    extern __shared__ unsigned gsm[];
    unsigned* As = gsm;             // [3][128][20]
    unsigned* Bs = gsm + 3 * GS;

    const int tid  = threadIdx.x;
    const int warp = tid >> 5, lane = tid & 31;
    const int wm = warp >> 1, wn = warp & 1;
    const int g  = lane >> 2, tg = lane & 3;
    const int lm = lane >> 3, lr = lane & 7;
    const int brow = blockIdx.y << 7, bcol = blockIdx.x << 7;

    float acc[2][8][4];
    #pragma unroll
    for (int i = 0; i < 2; i++)
        #pragma unroll
        for (int j = 0; j < 8; j++)
            #pragma unroll
            for (int k = 0; k < 4; k++) acc[i][j][k] = 0.f;

    const int arow = tid >> 1;            // tile row (A and BT)
    const int akp  = (tid & 1) << 3;      // word offset 0 / 8

    auto issue = [&](int kt) {
        const int st = (kt % 3) * GS + arow * 20 + akp;
        const char* ga = (const char*)(A  + (size_t)(brow + arow) * K + kt * 32 + akp * 2);
        const char* gb = (const char*)(BT + (size_t)(bcol + arow) * K + kt * 32 + akp * 2);
        cpa(&As[st],     ga);
        cpa(&As[st + 4], ga + 16);
        cpa(&Bs[st],     gb);
        cpa(&Bs[st + 4], gb + 16);
    };
    auto compute = [&](int buf) {
        const unsigned* Ab = As + buf * GS;
        const unsigned* Bb = Bs + buf * GS;
        #pragma unroll
        for (int step = 0; step < 2; step++) {
            const int lcol = (step << 3) + ((lm >> 1) << 2);
            unsigned af[2][4];
            #pragma unroll
            for (int mt = 0; mt < 2; mt++) {
                const int row = (wm << 5) + (mt << 4) + ((lm & 1) << 3) + lr;
                ldsm4(af[mt], &Ab[row * 20 + lcol]);
            }
            unsigned bfg[8][2];
            #pragma unroll
            for (int np = 0; np < 4; np++) {
                const int row = (wn << 6) + (np << 4) + ((lm & 1) << 3) + lr;
                unsigned t[4];
                ldsm4(t, &Bb[row * 20 + lcol]);
                bfg[np*2][0]   = t[0]; bfg[np*2+1][0] = t[1];
                bfg[np*2][1]   = t[2]; bfg[np*2+1][1] = t[3];
            }
            #pragma unroll
            for (int mt = 0; mt < 2; mt++)
                #pragma unroll
                for (int nt = 0; nt < 8; nt++)
                    mma16(acc[mt][nt], af[mt], bfg[nt]);
        }
    };

    const int nk = K >> 5;
    issue(0); CP_COMMIT();
    issue(1); CP_COMMIT();
    for (int kt = 0; kt < nk; kt++) {
        CP_WAIT(1);
        __syncthreads();
        if (kt + 2 < nk) issue(kt + 2);
        CP_COMMIT();                       // always commit: keeps group count exact
        compute(kt % 3);
    }

    // epilogue
    #pragma unroll
    for (int mt = 0; mt < 2; mt++) {
        #pragma unroll
        for (int nt = 0; nt < 8; nt++) {
            const int r0 = brow + (wm << 5) + (mt << 4) + g;
            const int c0 = bcol + (wn << 6) + (nt << 3) + (tg << 1);
            const float b0 = bias[c0], b1 = bias[c0 + 1];
            const float v00 = acc[mt][nt][0] + b0, v01 = acc[mt][nt][1] + b1;
            const float v10 = acc[mt][nt][2] + b0, v11 = acc[mt][nt][3] + b1;
            if (mode == 0) {
                *reinterpret_cast<float2*>(&C[(size_t)r0 * N + c0])       = make_float2(v00, v01);
                *reinterpret_cast<float2*>(&C[(size_t)(r0 + 8) * N + c0]) = make_float2(v10, v11);
            } else if (mode == 1) {
                const int which = c0 >> 10;
                const int h = (c0 >> 6) & 15;
                const int d = c0 & 63;
                unsigned* dst = (which == 0) ? g_q : (which == 1) ? g_k : g_v;
                #pragma unroll
                for (int rr = 0; rr < 2; rr++) {
                    const int r = r0 + rr * 8;
                    const int b = r >> 11, s = r & 2047;
                    const size_t idx = (((size_t)((b * HH + h) * SS + s)) * HD + d) >> 1;
                    dst[idx] = rr ? pk(v10, v11) : pk(v00, v01);
                }
            } else {
                #pragma unroll
                for (int rr = 0; rr < 2; rr++) {
                    const int r = r0 + rr * 8;
                    const float ga = rr ? v10 : v00, gb = rr ? v11 : v01;
                    const size_t off = (size_t)r * N + c0;
                    const float2 ov = *reinterpret_cast<const float2*>(&fuse_o[off]);
                    const float2 xv = *reinterpret_cast<const float2*>(&fuse_x[off]);
                    float2 res;
                    res.x = ov.x / (1.f + ex2(-ga * 1.44269504f)) + xv.x;
                    res.y = ov.y / (1.f + ex2(-gb * 1.44269504f)) + xv.y;
                    *reinterpret_cast<float2*>(&C[off]) = res;
                }
            }
        }
    }
}

// ---------------- flash attention: cp.async double buffer, ldmatrix.trans V ------
#define CEXP (0.125f * 1.44269504088896f)
#define NT (SS / 64)

__global__ __launch_bounds__(256) void attn_kernel()
{
    __shared__ unsigned Ks[2][64][36];   // [buf][key][hd word]
    __shared__ unsigned Vs[2][64][36];   // [buf][key][hd word]

    const int tid  = threadIdx.x;
    const int warp = tid >> 5, lane = tid & 31;
    const int g  = lane >> 2, tg = lane & 3;
    const int lm = lane >> 3, lr = lane & 7;
    const int bh = blockIdx.y;
    const int q0 = blockIdx.x << 7;
    const int mr0 = warp << 4;             // 16 q-rows per warp

    const unsigned* Qg = g_q + (size_t)bh * SS * 32;   // 32 words/row
    const unsigned* Kg = g_k + (size_t)bh * SS * 32;
    const unsigned* Vg = g_v + (size_t)bh * SS * 32;

    // ---- Q fragments in registers ----
    unsigned qf[4][4];
    {
        const unsigned* r0p = Qg + (size_t)(q0 + mr0 + g) * 32;
        const unsigned* r1p = Qg + (size_t)(q0 + mr0 + g + 8) * 32;
        #pragma unroll
        for (int kc = 0; kc < 4; kc++) {
            qf[kc][0] = r0p[kc*8 + tg];
            qf[kc][1] = r1p[kc*8 + tg];
            qf[kc][2] = r0p[kc*8 + tg + 4];
            qf[kc][3] = r1p[kc*8 + tg + 4];
        }
    }

    float m0 = -1e30f, m1 = -1e30f, l0 = 0.f, l1 = 0.f;
    float oacc[8][4];
    #pragma unroll
    for (int j = 0; j < 8; j++)
        #pragma unroll
        for (int k = 0; k < 4; k++) oacc[j][k] = 0.f;

    const int ld_row = tid >> 2, ld_wo = (tid & 3) << 3;   // 64 rows x 32 words

    auto load = [&](int kt) {
        const int buf = kt & 1;
        const char* gk = (const char*)(Kg + (size_t)(kt * 64 + ld_row) * 32 + ld_wo);
        const char* gv = (const char*)(Vg + (size_t)(kt * 64 + ld_row) * 32 + ld_wo);
        cpa(&Ks[buf][ld_row][ld_wo],     gk);
        cpa(&Ks[buf][ld_row][ld_wo + 4], gk + 16);
        cpa(&Vs[buf][ld_row][ld_wo],     gv);
        cpa(&Vs[buf][ld_row][ld_wo + 4], gv + 16);
    };

    load(0); CP_COMMIT();
    for (int kt = 0; kt < NT; kt++) {
        const int buf = kt & 1;
        CP_WAIT(0);
        __syncthreads();                        // tile kt ready; prev compute done
        if (kt + 1 < NT) { load(kt + 1); CP_COMMIT(); }   // overlaps compute below

        // ---- S = Q K^T : 16 rows x 64 keys, k = 64 ----
        float sacc[8][4];
        #pragma unroll
        for (int j = 0; j < 8; j++)
            #pragma unroll
            for (int k = 0; k < 4; k++) sacc[j][k] = 0.f;

        #pragma unroll
        for (int kc = 0; kc < 4; kc++) {
            const int lcol = kc*8 + ((lm >> 1) << 2);
            #pragma unroll
            for (int np = 0; np < 4; np++) {
                unsigned t[4];
                ldsm4(t, &Ks[buf][np*16 + ((lm & 1) << 3) + lr][lcol]);
                unsigned b0[2] = { t[0], t[2] };
                unsigned b1[2] = { t[1], t[3] };
                mma16(sacc[np*2],     qf[kc], b0);
                mma16(sacc[np*2 + 1], qf[kc], b1);
            }
        }

        // ---- register online softmax ----
        float mx0 = sacc[0][0], mx1 = sacc[0][2];
        #pragma unroll
        for (int nt = 0; nt < 8; nt++) {
            mx0 = fmaxf(mx0, fmaxf(sacc[nt][0], sacc[nt][1]));
            mx1 = fmaxf(mx1, fmaxf(sacc[nt][2], sacc[nt][3]));
        }
        mx0 = fmaxf(mx0, __shfl_xor_sync(0xFFFFFFFFu, mx0, 1));
        mx0 = fmaxf(mx0, __shfl_xor_sync(0xFFFFFFFFu, mx0, 2));
        mx1 = fmaxf(mx1, __shfl_xor_sync(0xFFFFFFFFu, mx1, 1));
        mx1 = fmaxf(mx1, __shfl_xor_sync(0xFFFFFFFFu, mx1, 2));
        const float M0 = fmaxf(m0, mx0), M1 = fmaxf(m1, mx1);
        const float f0 = ex2((m0 - M0) * CEXP), f1 = ex2((m1 - M1) * CEXP);
        m0 = M0; m1 = M1;

        float sum0 = 0.f, sum1 = 0.f;
        #pragma unroll
        for (int nt = 0; nt < 8; nt++) {
            const float p0 = ex2((sacc[nt][0] - M0) * CEXP);
            const float p1 = ex2((sacc[nt][1] - M0) * CEXP);
            const float p2 = ex2((sacc[nt][2] - M1) * CEXP);
            const float p3 = ex2((sacc[nt][3] - M1) * CEXP);
            sacc[nt][0] = p0; sacc[nt][1] = p1; sacc[nt][2] = p2; sacc[nt][3] = p3;
            sum0 += p0 + p1; sum1 += p2 + p3;
        }
        sum0 += __shfl_xor_sync(0xFFFFFFFFu, sum0, 1);
        sum0 += __shfl_xor_sync(0xFFFFFFFFu, sum0, 2);
        sum1 += __shfl_xor_sync(0xFFFFFFFFu, sum1, 1);
        sum1 += __shfl_xor_sync(0xFFFFFFFFu, sum1, 2);
        l0 = l0 * f0 + sum0;
        l1 = l1 * f1 + sum1;

        #pragma unroll
        for (int nt = 0; nt < 8; nt++) {
            oacc[nt][0] *= f0; oacc[nt][1] *= f0;
            oacc[nt][2] *= f1; oacc[nt][3] *= f1;
        }

        // pack P fragments straight from S registers
        unsigned pf[4][4];
        #pragma unroll
        for (int kc = 0; kc < 4; kc++) {
            pf[kc][0] = pk(sacc[2*kc][0],     sacc[2*kc][1]);
            pf[kc][1] = pk(sacc[2*kc][2],     sacc[2*kc][3]);
            pf[kc][2] = pk(sacc[2*kc + 1][0], sacc[2*kc + 1][1]);
            pf[kc][3] = pk(sacc[2*kc + 1][2], sacc[2*kc + 1][3]);
        }

        // ---- O += P V : V b-frags via ldmatrix.x4.trans ----
        #pragma unroll
        for (int kc = 0; kc < 4; kc++) {
            const int vrow = kc*16 + ((lm & 1) << 3) + lr;
            #pragma unroll
            for (int np2 = 0; np2 < 4; np2++) {
                const int vcol = np2*8 + ((lm >> 1) << 2);
                unsigned t[4];
                ldsm4t(t, &Vs[buf][vrow][vcol]);
                unsigned b0[2] = { t[0], t[1] };
                unsigned b1[2] = { t[2], t[3] };
                mma16(oacc[np2*2],     pf[kc], b0);
                mma16(oacc[np2*2 + 1], pf[kc], b1);
            }
        }
    }

    // ---- normalize + write ctx bf16 in [B,S,D] ----
    const int b = bh >> 4, h = bh & 15;
    const float inv0 = 1.f / l0, inv1 = 1.f / l1;
    const size_t row0 = (size_t)(b * SS + q0 + mr0 + g)     * (DD/2) + h * (HD/2);
    const size_t row1 = (size_t)(b * SS + q0 + mr0 + g + 8) * (DD/2) + h * (HD/2);
    #pragma unroll
    for (int nt = 0; nt < 8; nt++) {
        g_ctx[row0 + nt*4 + tg] = pk(oacc[nt][0] * inv0, oacc[nt][1] * inv0);
        g_ctx[row1 + nt*4 + tg] = pk(oacc[nt][2] * inv1, oacc[nt][3] * inv1);
    }
}

// ---------------- launch ----------------
extern "C" void kernel_launch(void* const* d_in, const int* in_sizes, int n_in,
                              void* d_out, int out_size)
{
    const float* x      = (const float*)d_in[0];
    const float* gamma  = (const float*)d_in[1];
    const float* beta   = (const float*)d_in[2];
    const float* w_qkv  = (const float*)d_in[3];
    const float* b_qkv  = (const float*)d_in[4];
    const float* w_out  = (const float*)d_in[5];
    const float* b_out  = (const float*)d_in[6];
    const float* w_gate = (const float*)d_in[7];
    const float* b_gate = (const float*)d_in[8];
    float* out = (float*)d_out;

    void *p_xn, *p_ctx, *p_outb, *p_wq, *p_wo, *p_wg;
    cudaGetSymbolAddress(&p_xn,   g_xn);
    cudaGetSymbolAddress(&p_ctx,  g_ctx);
    cudaGetSymbolAddress(&p_outb, g_outb);
    cudaGetSymbolAddress(&p_wq,   g_wqT);
    cudaGetSymbolAddress(&p_wo,   g_woT);
    cudaGetSymbolAddress(&p_wg,   g_wgT);

    cudaFuncSetAttribute(gemm_bf16,
                         cudaFuncAttributeMaxDynamicSharedMemorySize,
                         GEMM_SMEM_BYTES);

    ln_kernel<<<MROWS, 256>>>(x, gamma, beta);

    wconv_all<<<dim3(160, 32), dim3(32, 8)>>>(w_qkv, w_out, w_gate);

    // QKV: [4096,1024] x [3072,1024]^T -> scatter bf16 q/k/v
    gemm_bf16<<<dim3(3 * DD / 128, MROWS / 128), 256, GEMM_SMEM_BYTES>>>(
        (const __nv_bfloat16*)p_xn, (const __nv_bfloat16*)p_wq, b_qkv,
        nullptr, nullptr, nullptr, MROWS, 3 * DD, DD, 1);

    attn_kernel<<<dim3(SS / 128, BB * HH), 256>>>();

    // out proj -> f32 scratch
    gemm_bf16<<<dim3(DD / 128, MROWS / 128), 256, GEMM_SMEM_BYTES>>>(
        (const __nv_bfloat16*)p_ctx, (const __nv_bfloat16*)p_wo, b_out,
        (float*)p_outb, nullptr, nullptr, MROWS, DD, DD, 0);

    // gate proj fused with out*sigmoid(gate)+x -> d_out
    gemm_bf16<<<dim3(DD / 128, MROWS / 128), 256, GEMM_SMEM_BYTES>>>(
        (const __nv_bfloat16*)p_xn, (const __nv_bfloat16*)p_wg, b_gate,
        out, (const float*)p_outb, x, MROWS, DD, DD, 2);
}